// round 6
// baseline (speedup 1.0000x reference)
#include <cuda_runtime.h>
#include <cstdint>
#include <cstddef>

#define NB      32
#define NTOK    576
#define DIM     1024
#define K_SEL   128
#define CPB     4     // CTAs per batch in greedy
#define RPC     144   // rows per CTA (576/4)
#define RPW     8     // rows per warp in init scan (144 / 18 warps)
#define NWARP   18

// ---------------- device scratch (static: allocation-free rule) ----------------
__device__ float g_nrm[(size_t)NB * NTOK * DIM];          // 75.5 MB normalized feats
__device__ float g_sim[(size_t)NB * NTOK * NTOK];         // 42.5 MB similarity
__device__ int   g_selint[NB * K_SEL];                    // selected idx (+1), step order
__device__ int   g_sorted[NB * K_SEL];                    // sorted selected idx
__device__ float g_cand_v[NB * 2 * CPB];                  // per-CTA argmax value (double buffered)
__device__ int   g_cand_i[NB * 2 * CPB];                  // per-CTA argmax index
__device__ int   g_done[NB * CPB];                        // monotonic step counters

__device__ __forceinline__ int ld_acq(const int* p) {
    int v;
    asm volatile("ld.acquire.gpu.b32 %0, [%1];" : "=r"(v) : "l"(p) : "memory");
    return v;
}
__device__ __forceinline__ void st_rel(int* p, int v) {
    asm volatile("st.release.gpu.b32 [%0], %1;" :: "l"(p), "r"(v) : "memory");
}
__device__ __forceinline__ float neg_inf() { return __int_as_float(0xff800000); }

// ---------------- kernel 0: reset inter-CTA sync state ----------------
__global__ void init_k() {
    int t = threadIdx.x;
    if (t < NB * CPB) g_done[t] = 0;
}

// ---------------- kernel 1: row L2-normalize (skips CLS token) ----------------
__global__ void norm_k(const float* __restrict__ hs) {
    int n = blockIdx.x, b = blockIdx.y, t = threadIdx.x;  // 256 threads, one float4 each
    const float4* src = (const float4*)(hs + ((size_t)b * (NTOK + 1) + n + 1) * DIM);
    float4 v = src[t];
    float s = v.x * v.x + v.y * v.y + v.z * v.z + v.w * v.w;
    __shared__ float red[8];
    __shared__ float nrm_s;
    #pragma unroll
    for (int o = 16; o; o >>= 1) s += __shfl_xor_sync(0xffffffffu, s, o);
    if ((t & 31) == 0) red[t >> 5] = s;
    __syncthreads();
    if (t == 0) {
        float tot = 0.f;
        #pragma unroll
        for (int w = 0; w < 8; w++) tot += red[w];
        nrm_s = sqrtf(tot);
    }
    __syncthreads();
    float nv = nrm_s;
    float4* dst = (float4*)(g_nrm + ((size_t)b * NTOK + n) * DIM);
    dst[t] = make_float4(v.x / nv, v.y / nv, v.z / nv, v.w / nv);
}

// ---------------- kernel 2: symmetric Gram GEMM, fp32 (unchanged, known-correct) ----------------
__global__ void gemm_k() {
    int b = blockIdx.y;
    int L = blockIdx.x;
    int i = 0;
    while (L >= 9 - i) { L -= 9 - i; i++; }
    int j = i + L;

    const float* A = g_nrm + (size_t)b * NTOK * DIM;
    __shared__ float As[16][68];
    __shared__ float Bs[16][68];

    int tid = threadIdx.x;
    int tx = tid & 15, ty = tid >> 4;
    int lrow = tid >> 2, lseg = tid & 3;

    float acc[4][4] = {};
    const float* aG = A + (size_t)(i * 64 + lrow) * DIM + lseg * 4;
    const float* bG = A + (size_t)(j * 64 + lrow) * DIM + lseg * 4;

    for (int k0 = 0; k0 < DIM; k0 += 16) {
        float4 av = *(const float4*)(aG + k0);
        float4 bv = *(const float4*)(bG + k0);
        __syncthreads();
        As[lseg * 4 + 0][lrow] = av.x;
        As[lseg * 4 + 1][lrow] = av.y;
        As[lseg * 4 + 2][lrow] = av.z;
        As[lseg * 4 + 3][lrow] = av.w;
        Bs[lseg * 4 + 0][lrow] = bv.x;
        Bs[lseg * 4 + 1][lrow] = bv.y;
        Bs[lseg * 4 + 2][lrow] = bv.z;
        Bs[lseg * 4 + 3][lrow] = bv.w;
        __syncthreads();
        #pragma unroll
        for (int k = 0; k < 16; k++) {
            float4 a = *(const float4*)&As[k][tx * 4];
            float4 bq = *(const float4*)&Bs[k][ty * 4];
            acc[0][0] += a.x * bq.x; acc[0][1] += a.x * bq.y; acc[0][2] += a.x * bq.z; acc[0][3] += a.x * bq.w;
            acc[1][0] += a.y * bq.x; acc[1][1] += a.y * bq.y; acc[1][2] += a.y * bq.z; acc[1][3] += a.y * bq.w;
            acc[2][0] += a.z * bq.x; acc[2][1] += a.z * bq.y; acc[2][2] += a.z * bq.z; acc[2][3] += a.z * bq.w;
            acc[3][0] += a.w * bq.x; acc[3][1] += a.w * bq.y; acc[3][2] += a.w * bq.z; acc[3][3] += a.w * bq.w;
        }
    }

    float* C = g_sim + (size_t)b * NTOK * NTOK;
    int r0 = i * 64 + tx * 4;
    int c0 = j * 64 + ty * 4;
    #pragma unroll
    for (int p = 0; p < 4; p++) {
        *(float4*)&C[(size_t)(r0 + p) * NTOK + c0] =
            make_float4(acc[p][0], acc[p][1], acc[p][2], acc[p][3]);
    }
    #pragma unroll
    for (int q = 0; q < 4; q++) {
        *(float4*)&C[(size_t)(c0 + q) * NTOK + r0] =
            make_float4(acc[0][q], acc[1][q], acc[2][q], acc[3][q]);
    }
}

// ---------------- kernel 3: greedy SCOPE, incremental gains + fresh verification --------
// 4 CTAs per batch, 576 threads. CTA c owns rows [c*144, (c+1)*144).
// Incremental gains give candidate bounds; candidates within `margin` of the
// local max are re-evaluated FRESH (sum relu(sim - cmax), exact cmax) so the
// argmax decision carries no accumulated drift. Cross-CTA compare uses fresh
// values with lowest-global-index tie-break (matches jnp.argmax first-max).
__global__ void greedy_k(const float* __restrict__ cls_attn,
                         float* __restrict__ idx_out, int write_idx) {
    int b = blockIdx.x >> 2;
    int c = blockIdx.x & 3;
    int t = threadIdx.x;
    int w = t >> 5, l = t & 31;

    __shared__ float cmax[NTOK];
    __shared__ float cls[RPC];
    __shared__ unsigned char sel[NTOK];
    __shared__ float gains[RPC];          // incremental raw relu-sums (bounds only)
    __shared__ float part[4 * RPC];       // per-group delta partials
    __shared__ unsigned short ch_idx[NTOK];
    __shared__ float ch_old[NTOK];
    __shared__ float ch_new[NTOK];
    __shared__ unsigned short cd_idx[RPC];
    __shared__ float cd_fresh[RPC];
    __shared__ int wcnt[NWARP], wbase[NWARP], cnt_s;
    __shared__ float M_s;
    __shared__ int best_s;

    cmax[t] = 0.f;
    sel[t] = 0;
    if (t < RPC) cls[t] = cls_attn[b * NTOK + c * RPC + t];
    __syncthreads();

    const float* simb = g_sim + (size_t)b * NTOK * NTOK;

    // ---- init: full scan once (cmax = 0) -> raw gains ----
    {
        int m0 = c * RPC + w * RPW;
        const float2* row2 = (const float2*)(simb + (size_t)m0 * NTOK);
        float acc[RPW];
        #pragma unroll
        for (int rr = 0; rr < RPW; rr++) acc[rr] = 0.f;
        #pragma unroll
        for (int it = 0; it < 9; it++) {
            int ci = it * 32 + l;
            #pragma unroll
            for (int rr = 0; rr < RPW; rr++) {
                float2 sv = row2[rr * (NTOK / 2) + ci];
                acc[rr] += fmaxf(sv.x, 0.f) + fmaxf(sv.y, 0.f);
            }
        }
        #pragma unroll
        for (int rr = 0; rr < RPW; rr++) {
            float a = acc[rr];
            #pragma unroll
            for (int o = 16; o; o >>= 1) a += __shfl_xor_sync(0xffffffffu, a, o);
            if (l == 0) gains[w * RPW + rr] = a;
        }
    }
    __syncthreads();

    int grp = t / RPC;          // 0..3
    int mm  = t - grp * RPC;    // 0..143

    for (int s = 0; s < K_SEL; s++) {
        // ---- step 1: local max of incremental (bound) values ----
        if (t < 32) {
            float bv = neg_inf();
            for (int ir = t; ir < RPC; ir += 32) {
                float v = sel[c * RPC + ir] ? neg_inf() : gains[ir] * cls[ir];
                bv = fmaxf(bv, v);
            }
            #pragma unroll
            for (int off = 16; off; off >>= 1)
                bv = fmaxf(bv, __shfl_down_sync(0xffffffffu, bv, off));
            if (t == 0) M_s = bv;
        }
        __syncthreads();

        // ---- step 2: build candidate list (within margin of local bound max) ----
        float M = M_s;
        float margin = 1e-2f + 1e-4f * fabsf(M);
        bool cand = false;
        if (t < RPC && !sel[c * RPC + t])
            cand = (gains[t] * cls[t] >= M - margin);
        unsigned cmsk = __ballot_sync(0xffffffffu, cand);
        if (l == 0) wcnt[w] = __popc(cmsk);
        __syncthreads();
        if (t == 0) {
            int sacc = 0;
            #pragma unroll
            for (int ww = 0; ww < NWARP; ww++) { wbase[ww] = sacc; sacc += wcnt[ww]; }
            cnt_s = sacc;
        }
        __syncthreads();
        if (cand) cd_idx[wbase[w] + __popc(cmsk & ((1u << l) - 1u))] = (unsigned short)t;
        __syncthreads();
        int ccnt = cnt_s;

        // ---- step 3: fresh recompute of candidate gains (one warp per candidate) ----
        for (int base = 0; base < ccnt; base += NWARP) {
            int ci = base + w;
            if (ci < ccnt) {
                int lr = cd_idx[ci];
                const float* row = simb + (size_t)(c * RPC + lr) * NTOK;
                float a = 0.f;
                #pragma unroll
                for (int k = 0; k < 18; k++) {
                    int col = k * 32 + l;
                    a += fmaxf(row[col] - cmax[col], 0.f);
                }
                #pragma unroll
                for (int o = 16; o; o >>= 1) a += __shfl_xor_sync(0xffffffffu, a, o);
                if (l == 0) cd_fresh[ci] = a * cls[lr];
            }
        }
        __syncthreads();

        // ---- step 4: argmax over fresh candidate values; cross-CTA exchange ----
        if (t < 32) {
            float bv = neg_inf();
            int bi = 0x7fffffff;
            for (int i = t; i < ccnt; i += 32) {
                float v = cd_fresh[i];
                int  ir = cd_idx[i];
                if (v > bv || (v == bv && ir < bi)) { bv = v; bi = ir; }
            }
            #pragma unroll
            for (int off = 16; off; off >>= 1) {
                float ov = __shfl_down_sync(0xffffffffu, bv, off);
                int   oi = __shfl_down_sync(0xffffffffu, bi, off);
                if (ov > bv || (ov == bv && oi < bi)) { bv = ov; bi = oi; }
            }
            if (t == 0) {
                int slot = (b * 2 + (s & 1)) * CPB + c;
                g_cand_v[slot] = bv;
                g_cand_i[slot] = c * RPC + bi;
                st_rel(&g_done[b * CPB + c], s + 1);
                for (int jj = 0; jj < CPB; jj++)
                    while (ld_acq(&g_done[b * CPB + jj]) < s + 1) {}
                float gbv = neg_inf();
                int gbi = 0x7fffffff;
                for (int jj = 0; jj < CPB; jj++) {
                    int sl = (b * 2 + (s & 1)) * CPB + jj;
                    float v = g_cand_v[sl];
                    int  ix = g_cand_i[sl];
                    if (v > gbv || (v == gbv && ix < gbi)) { gbv = v; gbi = ix; }
                }
                best_s = gbi;
                sel[gbi] = 1;
                if (c == 0) {
                    g_selint[b * K_SEL + s] = gbi + 1;
                    if (write_idx) idx_out[b * K_SEL + s] = (float)(gbi + 1);
                }
            }
        }
        __syncthreads();
        int best = best_s;
        if (s == K_SEL - 1) break;   // last selection needs no update

        // ---- phase A: changed-column list from row `best` (deterministic order) ----
        float v = simb[(size_t)best * NTOK + t];
        float old = cmax[t];
        bool ch = v > old;
        unsigned msk = __ballot_sync(0xffffffffu, ch);
        if (l == 0) wcnt[w] = __popc(msk);
        __syncthreads();
        if (t == 0) {
            int sacc = 0;
            #pragma unroll
            for (int ww = 0; ww < NWARP; ww++) { wbase[ww] = sacc; sacc += wcnt[ww]; }
            cnt_s = sacc;
        }
        __syncthreads();
        if (ch) {
            int pos = wbase[w] + __popc(msk & ((1u << l) - 1u));
            ch_idx[pos] = (unsigned short)t;
            ch_old[pos] = old;
            ch_new[pos] = v;
            cmax[t] = v;
        }
        __syncthreads();
        int cnt = cnt_s;

        // ---- phase B: apply deltas to incremental gains ----
        float pa = 0.f;
        for (int i = grp; i < cnt; i += 4) {
            int   n  = ch_idx[i];
            float o  = ch_old[i];
            float nw = ch_new[i];
            float x  = simb[(size_t)n * NTOK + c * RPC + mm];
            pa += fmaxf(x - o, 0.f) - fmaxf(x - nw, 0.f);   // >= 0
        }
        part[grp * RPC + mm] = pa;
        __syncthreads();
        if (t < RPC) {
            float d = ((part[t] + part[RPC + t]) + part[2 * RPC + t]) + part[3 * RPC + t];
            gains[t] -= d;
        }
        __syncthreads();
    }
}

// ---------------- kernel 4: rank-sort the 128 selected indices per batch ----------------
__global__ void sort_k() {
    int b = blockIdx.x, t = threadIdx.x;
    __shared__ int ids[K_SEL];
    ids[t] = g_selint[b * K_SEL + t];
    __syncthreads();
    int v = ids[t];
    int rank = 0;
    for (int j = 0; j < K_SEL; j++) rank += (ids[j] < v);
    g_sorted[b * K_SEL + rank] = v;   // indices unique -> rank is a permutation
}

// ---------------- kernel 5: gather dominant tokens ----------------
__global__ void gather_k(const float* __restrict__ hs, float* __restrict__ out) {
    int k = blockIdx.x, b = blockIdx.y, t = threadIdx.x;  // 256 threads, float4 each
    int src = g_sorted[b * K_SEL + k];
    const float4* sp = (const float4*)(hs + ((size_t)b * (NTOK + 1) + src) * DIM);
    float4* dp = (float4*)(out + ((size_t)b * K_SEL + k) * DIM);
    dp[t] = sp[t];
}

// ---------------- launch ----------------
extern "C" void kernel_launch(void* const* d_in, const int* in_sizes, int n_in,
                              void* d_out, int out_size) {
    const float* hs  = (const float*)d_in[0];   // [32, 577, 1024] f32
    const float* cls = (const float*)d_in[1];   // [32, 576] f32
    float* out = (float*)d_out;

    const int tok_elems = NB * K_SEL * DIM;     // 4,194,304
    int write_idx = (out_size >= tok_elems + NB * K_SEL) ? 1 : 0;
    float* idx_out = out + tok_elems;

    init_k<<<1, 128>>>();
    norm_k<<<dim3(NTOK, NB), 256>>>(hs);
    gemm_k<<<dim3(45, NB), 256>>>();
    greedy_k<<<NB * CPB, NTOK>>>(cls, idx_out, write_idx);
    sort_k<<<NB, K_SEL>>>();
    gather_k<<<dim3(K_SEL, NB), 256>>>(hs, out);
}